// round 4
// baseline (speedup 1.0000x reference)
#include <cuda_runtime.h>
#include <cstdint>

#define D 4096
#define NV4 (D / 4)          // 1024 float4 per row
#define THREADS 256
#define ROWS_PER_CTA 8
#define EPS 1e-6f

__device__ __forceinline__ void prefetch_row(float4* sbuf, const float4* xr, int t)
{
    uint32_t s0 = (uint32_t)__cvta_generic_to_shared(&sbuf[t]);
    uint32_t s1 = (uint32_t)__cvta_generic_to_shared(&sbuf[t + THREADS]);
    uint32_t s2 = (uint32_t)__cvta_generic_to_shared(&sbuf[t + 2 * THREADS]);
    uint32_t s3 = (uint32_t)__cvta_generic_to_shared(&sbuf[t + 3 * THREADS]);
    asm volatile("cp.async.cg.shared.global [%0], [%1], 16;\n"
                 "cp.async.cg.shared.global [%2], [%3], 16;\n"
                 "cp.async.cg.shared.global [%4], [%5], 16;\n"
                 "cp.async.cg.shared.global [%6], [%7], 16;\n"
                 "cp.async.commit_group;\n"
                 :: "r"(s0), "l"(&xr[t]),
                    "r"(s1), "l"(&xr[t + THREADS]),
                    "r"(s2), "l"(&xr[t + 2 * THREADS]),
                    "r"(s3), "l"(&xr[t + 3 * THREADS]));
}

__global__ __launch_bounds__(THREADS, 6) void mrmsnorm_kernel(
    const float4* __restrict__ x,
    const float4* __restrict__ scale,
    float4* __restrict__ out)
{
    __shared__ float4 sx[2][NV4];    // 2 x 16 KB double buffer
    __shared__ float ws[8][3];

    const int t = threadIdx.x;
    const int warp = t >> 5;
    const int lane = t & 31;

    const size_t row0 = (size_t)blockIdx.x * ROWS_PER_CTA;

    // Prologue: prefetch first row into buffer 0.
    prefetch_row(sx[0], x + row0 * NV4, t);

    #pragma unroll 1
    for (int i = 0; i < ROWS_PER_CTA; i++) {
        const int cur = i & 1;
        const int nxt = cur ^ 1;

        // Overlap: issue next row's loads before consuming current row.
        if (i + 1 < ROWS_PER_CTA) {
            prefetch_row(sx[nxt], x + (row0 + i + 1) * NV4, t);
            asm volatile("cp.async.wait_group 1;");   // current row complete
        } else {
            asm volatile("cp.async.wait_group 0;");
        }
        // sx access pattern is thread-private (thread t wrote exactly the
        // indices it reads), so no barrier needed for data visibility here.

        const float4* __restrict__ sb = sx[cur];

        // Pass 1: per-slice sum-of-squares.
        float sa, sbv, scd;
        {
            float4 a = sb[t];
            float4 b = sb[t + THREADS];
            float4 c = sb[t + 2 * THREADS];
            float4 d = sb[t + 3 * THREADS];
            sa  = a.x * a.x + a.y * a.y + a.z * a.z + a.w * a.w;
            sbv = b.x * b.x + b.y * b.y + b.z * b.z + b.w * b.w;
            float sc = c.x * c.x + c.y * c.y + c.z * c.z + c.w * c.w;
            float sd = d.x * d.x + d.y * d.y + d.z * d.z + d.w * d.w;
            scd = sc + sd;
        }

        #pragma unroll
        for (int o = 16; o > 0; o >>= 1) {
            sa  += __shfl_down_sync(0xffffffffu, sa, o);
            sbv += __shfl_down_sync(0xffffffffu, sbv, o);
            scd += __shfl_down_sync(0xffffffffu, scd, o);
        }

        if (lane == 0) {
            ws[warp][0] = sa;
            ws[warp][1] = sbv;
            ws[warp][2] = scd;
        }
        __syncthreads();

        // Segment sums: seg0 [0,64), seg1 [64,128), seg2 [128,256),
        // seg3 [256,512), seg4 [512,1024)  (float4 indices).
        float seg0 = ws[0][0] + ws[1][0];
        float seg1 = ws[2][0] + ws[3][0];
        float seg2 = ws[4][0] + ws[5][0] + ws[6][0] + ws[7][0];
        float seg3 = ws[0][1] + ws[1][1] + ws[2][1] + ws[3][1]
                   + ws[4][1] + ws[5][1] + ws[6][1] + ws[7][1];
        float seg4 = ws[0][2] + ws[1][2] + ws[2][2] + ws[3][2]
                   + ws[4][2] + ws[5][2] + ws[6][2] + ws[7][2];

        float c0 = seg0;
        float c1 = c0 + seg1;
        float c2 = c1 + seg2;
        float c3 = c2 + seg3;
        float c4 = c3 + seg4;

        float r0v = rsqrtf(c0 * (1.0f / 256.0f)  + EPS);
        float r1v = rsqrtf(c1 * (1.0f / 512.0f)  + EPS);
        float r2v = rsqrtf(c2 * (1.0f / 1024.0f) + EPS);
        float r3v = rsqrtf(c3 * (1.0f / 2048.0f) + EPS);
        float r4v = rsqrtf(c4 * (1.0f / 4096.0f) + EPS);

        float ra = (t < 64) ? r0v : (t < 128) ? r1v : r2v;  // warp-uniform
        float rb = r3v;
        float rc = r4v;

        // Pass 2: scale + streaming store.
        float4* __restrict__ orow = out + (row0 + i) * NV4;
        {
            float4 a = sb[t];
            float4 s = __ldg(&scale[t]);
            float4 o;
            o.x = a.x * ra * s.x;  o.y = a.y * ra * s.y;
            o.z = a.z * ra * s.z;  o.w = a.w * ra * s.w;
            __stcs(&orow[t], o);
        }
        {
            float4 a = sb[t + THREADS];
            float4 s = __ldg(&scale[t + THREADS]);
            float4 o;
            o.x = a.x * rb * s.x;  o.y = a.y * rb * s.y;
            o.z = a.z * rb * s.z;  o.w = a.w * rb * s.w;
            __stcs(&orow[t + THREADS], o);
        }
        {
            float4 a = sb[t + 2 * THREADS];
            float4 s = __ldg(&scale[t + 2 * THREADS]);
            float4 o;
            o.x = a.x * rc * s.x;  o.y = a.y * rc * s.y;
            o.z = a.z * rc * s.z;  o.w = a.w * rc * s.w;
            __stcs(&orow[t + 2 * THREADS], o);
        }
        {
            float4 a = sb[t + 3 * THREADS];
            float4 s = __ldg(&scale[t + 3 * THREADS]);
            float4 o;
            o.x = a.x * rc * s.x;  o.y = a.y * rc * s.y;
            o.z = a.z * rc * s.z;  o.w = a.w * rc * s.w;
            __stcs(&orow[t + 3 * THREADS], o);
        }

        // Covers: ws WAR (next iter rewrites ws) and sx WAR (the prefetch at
        // iter i+1 writes sx[cur], which other warps may not have finished
        // reading — barrier orders all pass-2 reads before the next cp.async).
        __syncthreads();
    }
}

extern "C" void kernel_launch(void* const* d_in, const int* in_sizes, int n_in,
                              void* d_out, int out_size)
{
    const float4* x = (const float4*)d_in[0];
    const float4* scale = (const float4*)d_in[1];
    float4* out = (float4*)d_out;

    const int rows = out_size / D;            // 16384
    const int grid = rows / ROWS_PER_CTA;     // 2048
    mrmsnorm_kernel<<<grid, THREADS>>>(x, scale, out);
}